// round 11
// baseline (speedup 1.0000x reference)
#include <cuda_runtime.h>
#include <cuda_bf16.h>
#include <math.h>

// Problem constants
constexpr int Bb   = 32;          // batch
constexpr int HW   = 1024;        // H*W tokens per batch
constexpr int C    = 512;         // channels
constexpr int G    = 8;           // groups
constexpr int CG   = C / G;       // 64 channels per group
constexpr int NTOK = Bb * HW;     // 32768 total tokens
constexpr int QKVN = 3 * C;       // 1536
constexpr float EPS = 1e-3f;

// Scratch (device globals -> allowed; no allocations). ~384 MB total.
__device__ float g_h [ (long)NTOK * C ];           // 64 MB (normed in, then attn out)
__device__ float g_q [ (long)NTOK * C ];           // 64 MB
__device__ float g_k [ (long)NTOK * C ];           // 64 MB
__device__ float g_v [ (long)NTOK * C ];           // 64 MB
__device__ float g_scores[ (long)Bb * HW * HW ];   // 128 MB (holds exp(scale*s))
__device__ float g_rowsum[ NTOK ];                 // 128 KB per-row sum of exp

// ---------------------------------------------------------------------------
// Zero the row-sum accumulator (must run every launch; graph-replay safe).
// ---------------------------------------------------------------------------
__global__ void zero_rowsum_kernel()
{
    g_rowsum[blockIdx.x * 256 + threadIdx.x] = 0.0f;
}

// ---------------------------------------------------------------------------
// GroupNorm (float4 paths; 64-channel group slices are 16-float4 aligned)
// ---------------------------------------------------------------------------
__global__ void groupnorm_kernel(const float* __restrict__ x,
                                 const float* __restrict__ gamma,
                                 const float* __restrict__ beta)
{
    const int bg = blockIdx.x;
    const int b  = bg >> 3;
    const int g  = bg & 7;
    const int t  = threadIdx.x;         // 256 threads

    const long base = ((long)b * HW) * C + g * CG;

    __shared__ float s_sum[256];
    __shared__ float s_sq [256];

    float lsum = 0.f, lsq = 0.f;
    for (int idx = t; idx < HW * CG / 4; idx += 256) {
        int n  = idx >> 4;              // token
        int c4 = (idx & 15) * 4;        // channel (vec4) within group
        float4 v = *reinterpret_cast<const float4*>(&x[base + (long)n * C + c4]);
        lsum += v.x + v.y + v.z + v.w;
        lsq  += v.x*v.x + v.y*v.y + v.z*v.z + v.w*v.w;
    }
    s_sum[t] = lsum; s_sq[t] = lsq;
    __syncthreads();
    for (int s = 128; s > 0; s >>= 1) {
        if (t < s) { s_sum[t] += s_sum[t + s]; s_sq[t] += s_sq[t + s]; }
        __syncthreads();
    }
    const float inv_n = 1.0f / (HW * CG);
    const float mean  = s_sum[0] * inv_n;
    const float var   = s_sq[0] * inv_n - mean * mean;
    const float rstd  = rsqrtf(var + EPS);

    for (int idx = t; idx < HW * CG / 4; idx += 256) {
        int n  = idx >> 4;
        int c4 = (idx & 15) * 4;
        int gc = g * CG + c4;
        float4 v  = *reinterpret_cast<const float4*>(&x[base + (long)n * C + c4]);
        float4 gm = *reinterpret_cast<const float4*>(&gamma[gc]);
        float4 bt = *reinterpret_cast<const float4*>(&beta[gc]);
        float4 o;
        o.x = (v.x - mean) * rstd * gm.x + bt.x;
        o.y = (v.y - mean) * rstd * gm.y + bt.y;
        o.z = (v.z - mean) * rstd * gm.z + bt.z;
        o.w = (v.w - mean) * rstd * gm.w + bt.w;
        *reinterpret_cast<float4*>(&g_h[base + (long)n * C + c4]) = o;
    }
}

// ---------------------------------------------------------------------------
// TF32 tensor-core GEMM core, cp.async double-buffered.
// Block tile 128x128, BK=32, 256 threads = 8 warps (2x4), warp tile 64x32.
// Raw fp32 bits are fed to mma.tf32 (HW truncates mantissa).
// Smem: As[2][128][36]  (rows = M, cols = K, stride 36 => conflict-free frags)
//       NT-B (B=[N][K]): Bs[2][128][36] like A
//       NN-B (B=[K][N]): Bs[2][32][136] k-major (no transpose needed)
// ---------------------------------------------------------------------------
constexpr int BK   = 32;
constexpr int SLDA = 36;    // A / NT-B smem row stride (words)
constexpr int SLDB = 136;   // NN-B smem row stride (words)

constexpr int A_WORDS_BUF  = 128 * SLDA;          // 4608
constexpr int BNT_WORDS_BUF= 128 * SLDA;          // 4608
constexpr int BNN_WORDS_BUF= BK * SLDB;           // 4352
constexpr int SMEM_BYTES_NT = (2*A_WORDS_BUF + 2*BNT_WORDS_BUF) * 4;  // 73728
constexpr int SMEM_BYTES_NN = (2*A_WORDS_BUF + 2*BNN_WORDS_BUF) * 4;  // 71680

__device__ __forceinline__ void cp16(unsigned* dst_smem, const float* src) {
    unsigned s = (unsigned)__cvta_generic_to_shared(dst_smem);
    asm volatile("cp.async.cg.shared.global [%0], [%1], 16;" :: "r"(s), "l"(src));
}
__device__ __forceinline__ void cp_commit() {
    asm volatile("cp.async.commit_group;");
}
template<int N>
__device__ __forceinline__ void cp_wait() {
    asm volatile("cp.async.wait_group %0;" :: "n"(N));
}

__device__ __forceinline__ void mma_tf32(float c[4],
                                         unsigned a0, unsigned a1, unsigned a2, unsigned a3,
                                         unsigned b0, unsigned b1)
{
    asm("mma.sync.aligned.m16n8k8.row.col.f32.tf32.tf32.f32 "
        "{%0,%1,%2,%3},{%4,%5,%6,%7},{%8,%9},{%0,%1,%2,%3};"
        : "+f"(c[0]), "+f"(c[1]), "+f"(c[2]), "+f"(c[3])
        : "r"(a0), "r"(a1), "r"(a2), "r"(a3), "r"(b0), "r"(b1));
}

// TRANS_B=true : B is [K][N] row-major (NN gemm)
// TRANS_B=false: B is [N][K] row-major (NT gemm)
template<bool TRANS_B>
__device__ __forceinline__ void gemm_mma_core(const float* __restrict__ A,
                                              const float* __restrict__ B,
                                              int K, int lda, int ldb,
                                              float acc[4][4][4])
{
    extern __shared__ unsigned dynsmem[];
    unsigned* As = dynsmem;                          // 2 bufs
    unsigned* Bs = dynsmem + 2 * A_WORDS_BUF;        // 2 bufs

    const int tid  = threadIdx.x;
    const int lane = tid & 31;
    const int warp = tid >> 5;
    const int wm   = warp >> 2;        // 0..1
    const int wn   = warp & 3;         // 0..3
    const int lq   = lane >> 2;        // 0..7
    const int lr   = lane & 3;         // 0..3

    // ---- tile copy (cp.async, 16B chunks) ----
    auto copy_tiles = [&](int k0, int buf) {
        unsigned* as = As + buf * A_WORDS_BUF;
        #pragma unroll
        for (int it = 0; it < 4; it++) {
            int idx  = it * 256 + tid;
            int row  = idx >> 3;
            int col4 = (idx & 7) * 4;
            cp16(&as[row * SLDA + col4], &A[(long)row * lda + k0 + col4]);
        }
        if (TRANS_B) {
            unsigned* bs = Bs + buf * BNN_WORDS_BUF;
            #pragma unroll
            for (int it = 0; it < 4; it++) {
                int idx = it * 256 + tid;       // 0..1023
                int kr  = idx >> 5;             // 0..31
                int n4  = (idx & 31) * 4;       // 0..124
                cp16(&bs[kr * SLDB + n4], &B[(long)(k0 + kr) * ldb + n4]);
            }
        } else {
            unsigned* bs = Bs + buf * BNT_WORDS_BUF;
            #pragma unroll
            for (int it = 0; it < 4; it++) {
                int idx  = it * 256 + tid;
                int row  = idx >> 3;
                int col4 = (idx & 7) * 4;
                cp16(&bs[row * SLDA + col4], &B[(long)row * ldb + k0 + col4]);
            }
        }
    };

    // ---- compute one staged tile ----
    auto compute_tile = [&](int buf) {
        const unsigned* as = As + buf * A_WORDS_BUF;
        const unsigned* bs = Bs + buf * (TRANS_B ? BNN_WORDS_BUF : BNT_WORDS_BUF);
        #pragma unroll
        for (int kk = 0; kk < 4; kk++) {
            const int kb = kk * 8;
            unsigned af[4][4], bf[4][2];
            #pragma unroll
            for (int mf = 0; mf < 4; mf++) {
                const unsigned* ap = &as[(wm * 64 + mf * 16 + lq) * SLDA + kb + lr];
                af[mf][0] = ap[0];
                af[mf][1] = ap[8 * SLDA];
                af[mf][2] = ap[4];
                af[mf][3] = ap[8 * SLDA + 4];
            }
            #pragma unroll
            for (int nf = 0; nf < 4; nf++) {
                const int nn = wn * 32 + nf * 8 + lq;
                if (TRANS_B) {
                    bf[nf][0] = bs[(kb + lr)     * SLDB + nn];
                    bf[nf][1] = bs[(kb + lr + 4) * SLDB + nn];
                } else {
                    bf[nf][0] = bs[nn * SLDA + kb + lr];
                    bf[nf][1] = bs[nn * SLDA + kb + lr + 4];
                }
            }
            #pragma unroll
            for (int mf = 0; mf < 4; mf++)
                #pragma unroll
                for (int nf = 0; nf < 4; nf++)
                    mma_tf32(acc[mf][nf], af[mf][0], af[mf][1], af[mf][2], af[mf][3],
                             bf[nf][0], bf[nf][1]);
        }
    };

    const int nit = K / BK;
    copy_tiles(0, 0);
    cp_commit();
    for (int it = 0; it < nit; it++) {
        const int buf = it & 1;
        if (it + 1 < nit) {
            copy_tiles((it + 1) * BK, buf ^ 1);
            cp_commit();
            cp_wait<1>();
        } else {
            cp_wait<0>();
        }
        __syncthreads();
        compute_tile(buf);
        __syncthreads();
    }
}

// Epilogue coords: frag (mf,nf), lane: row = wm*64+mf*16+lane/4 (+8 for c2/c3),
//                  col = wn*32+nf*8+2*(lane%4) (+1 for c1/c3)

// ---------------------------------------------------------------------------
// QKV GEMM: [NTOK,512] x [512,1536] + bias -> g_q/g_k/g_v
// ---------------------------------------------------------------------------
__global__ __launch_bounds__(256) void qkv_gemm_kernel(const float* __restrict__ w,
                                                       const float* __restrict__ bias)
{
    const int n0 = blockIdx.x * 128;
    const int m0 = blockIdx.y * 128;
    float acc[4][4][4] = {};
    gemm_mma_core<true>(g_h + (long)m0 * C, w + n0, C, C, QKVN, acc);

    const int lane = threadIdx.x & 31, warp = threadIdx.x >> 5;
    const int wm = warp >> 2, wn = warp & 3;
    const int which = n0 >> 9;   // 0=q 1=k 2=v
    float* dst = (which == 0) ? g_q : (which == 1) ? g_k : g_v;
    #pragma unroll
    for (int mf = 0; mf < 4; mf++) {
        const int r0 = m0 + wm * 64 + mf * 16 + (lane >> 2);
        #pragma unroll
        for (int nf = 0; nf < 4; nf++) {
            const int n = n0 + wn * 32 + nf * 8 + 2 * (lane & 3);
            const int c = n & 511;
            float b0 = bias[n], b1 = bias[n + 1];
            *reinterpret_cast<float2*>(&dst[(long)r0 * C + c]) =
                make_float2(acc[mf][nf][0] + b0, acc[mf][nf][1] + b1);
            *reinterpret_cast<float2*>(&dst[(long)(r0 + 8) * C + c]) =
                make_float2(acc[mf][nf][2] + b0, acc[mf][nf][3] + b1);
        }
    }
}

// ---------------------------------------------------------------------------
// scores: p[b,m,n] = exp(scale * q.k) stored unnormalized; row sums via atomics.
// (Max-subtraction is unnecessary here: scores ~ N(0,1), |s| < ~6 << 88.)
// ---------------------------------------------------------------------------
__global__ __launch_bounds__(256) void scores_kernel()
{
    const int b  = blockIdx.z;
    const int n0 = blockIdx.x * 128;
    const int m0 = blockIdx.y * 128;
    const float scale = rsqrtf((float)C);

    float acc[4][4][4] = {};
    gemm_mma_core<false>(g_q + (long)b * HW * C + (long)m0 * C,
                         g_k + (long)b * HW * C + (long)n0 * C, C, C, C, acc);

    float* out = g_scores + (long)b * HW * HW;
    const int lane = threadIdx.x & 31, warp = threadIdx.x >> 5;
    const int wm = warp >> 2, wn = warp & 3;
    const int lr = lane & 3;
    #pragma unroll
    for (int mf = 0; mf < 4; mf++) {
        const int r0 = m0 + wm * 64 + mf * 16 + (lane >> 2);
        float sum0 = 0.f, sum8 = 0.f;
        #pragma unroll
        for (int nf = 0; nf < 4; nf++) {
            const int n = n0 + wn * 32 + nf * 8 + 2 * lr;
            float e0 = __expf(acc[mf][nf][0] * scale);
            float e1 = __expf(acc[mf][nf][1] * scale);
            float e2 = __expf(acc[mf][nf][2] * scale);
            float e3 = __expf(acc[mf][nf][3] * scale);
            *reinterpret_cast<float2*>(&out[(long)r0 * HW + n])       = make_float2(e0, e1);
            *reinterpret_cast<float2*>(&out[(long)(r0 + 8) * HW + n]) = make_float2(e2, e3);
            sum0 += e0 + e1;
            sum8 += e2 + e3;
        }
        // reduce over the 4 lanes sharing this row (lr = 0..3)
        #pragma unroll
        for (int o = 1; o < 4; o <<= 1) {
            sum0 += __shfl_xor_sync(0xffffffffu, sum0, o);
            sum8 += __shfl_xor_sync(0xffffffffu, sum8, o);
        }
        if (lr == 0) {
            atomicAdd(&g_rowsum[b * HW + r0],     sum0);
            atomicAdd(&g_rowsum[b * HW + r0 + 8], sum8);
        }
    }
}

// ---------------------------------------------------------------------------
// attention output: g_h[b,m,c] = (sum_n p[b,m,n] * v[b,n,c]) / rowsum[b,m]
// ---------------------------------------------------------------------------
__global__ __launch_bounds__(256) void av_kernel()
{
    const int b  = blockIdx.z;
    const int n0 = blockIdx.x * 128;   // channel tile
    const int m0 = blockIdx.y * 128;   // query tile

    float acc[4][4][4] = {};
    gemm_mma_core<true>(g_scores + (long)b * HW * HW + (long)m0 * HW,
                        g_v + (long)b * HW * C + n0, HW, HW, C, acc);

    float* out = g_h + (long)b * HW * C;
    const int lane = threadIdx.x & 31, warp = threadIdx.x >> 5;
    const int wm = warp >> 2, wn = warp & 3;
    #pragma unroll
    for (int mf = 0; mf < 4; mf++) {
        const int r0 = m0 + wm * 64 + mf * 16 + (lane >> 2);
        const float inv0 = 1.0f / g_rowsum[b * HW + r0];
        const float inv8 = 1.0f / g_rowsum[b * HW + r0 + 8];
        #pragma unroll
        for (int nf = 0; nf < 4; nf++) {
            const int n = n0 + wn * 32 + nf * 8 + 2 * (lane & 3);
            *reinterpret_cast<float2*>(&out[(long)r0 * C + n]) =
                make_float2(acc[mf][nf][0] * inv0, acc[mf][nf][1] * inv0);
            *reinterpret_cast<float2*>(&out[(long)(r0 + 8) * C + n]) =
                make_float2(acc[mf][nf][2] * inv8, acc[mf][nf][3] * inv8);
        }
    }
}

// ---------------------------------------------------------------------------
// proj + bias + residual: out = x + g_h @ w_proj + b_proj
// ---------------------------------------------------------------------------
__global__ __launch_bounds__(256) void proj_kernel(const float* __restrict__ x,
                                                   const float* __restrict__ w,
                                                   const float* __restrict__ bias,
                                                   float* __restrict__ out)
{
    const int n0 = blockIdx.x * 128;
    const int m0 = blockIdx.y * 128;
    float acc[4][4][4] = {};
    gemm_mma_core<true>(g_h + (long)m0 * C, w + n0, C, C, C, acc);

    const int lane = threadIdx.x & 31, warp = threadIdx.x >> 5;
    const int wm = warp >> 2, wn = warp & 3;
    #pragma unroll
    for (int mf = 0; mf < 4; mf++) {
        const int r0 = m0 + wm * 64 + mf * 16 + (lane >> 2);
        #pragma unroll
        for (int nf = 0; nf < 4; nf++) {
            const int n = n0 + wn * 32 + nf * 8 + 2 * (lane & 3);
            float b0 = bias[n], b1 = bias[n + 1];
            float2 x0 = *reinterpret_cast<const float2*>(&x[(long)r0 * C + n]);
            float2 x1 = *reinterpret_cast<const float2*>(&x[(long)(r0 + 8) * C + n]);
            *reinterpret_cast<float2*>(&out[(long)r0 * C + n]) =
                make_float2(acc[mf][nf][0] + b0 + x0.x, acc[mf][nf][1] + b1 + x0.y);
            *reinterpret_cast<float2*>(&out[(long)(r0 + 8) * C + n]) =
                make_float2(acc[mf][nf][2] + b0 + x1.x, acc[mf][nf][3] + b1 + x1.y);
        }
    }
}

// ---------------------------------------------------------------------------
extern "C" void kernel_launch(void* const* d_in, const int* in_sizes, int n_in,
                              void* d_out, int out_size)
{
    const float* x      = (const float*)d_in[0];
    const float* gamma  = (const float*)d_in[1];
    const float* beta   = (const float*)d_in[2];
    const float* w_qkv  = (const float*)d_in[3];
    const float* b_qkv  = (const float*)d_in[4];
    const float* w_proj = (const float*)d_in[5];
    const float* b_proj = (const float*)d_in[6];
    float* out = (float*)d_out;

    // Opt-in to >48KB dynamic smem (idempotent, capture-safe, no allocation).
    cudaFuncSetAttribute(qkv_gemm_kernel, cudaFuncAttributeMaxDynamicSharedMemorySize, SMEM_BYTES_NN);
    cudaFuncSetAttribute(scores_kernel,   cudaFuncAttributeMaxDynamicSharedMemorySize, SMEM_BYTES_NT);
    cudaFuncSetAttribute(av_kernel,       cudaFuncAttributeMaxDynamicSharedMemorySize, SMEM_BYTES_NN);
    cudaFuncSetAttribute(proj_kernel,     cudaFuncAttributeMaxDynamicSharedMemorySize, SMEM_BYTES_NN);

    zero_rowsum_kernel<<<NTOK / 256, 256>>>();
    groupnorm_kernel<<<Bb * G, 256>>>(x, gamma, beta);
    qkv_gemm_kernel<<<dim3(QKVN / 128, NTOK / 128), 256, SMEM_BYTES_NN>>>(w_qkv, b_qkv);
    scores_kernel<<<dim3(HW / 128, HW / 128, Bb), 256, SMEM_BYTES_NT>>>();
    av_kernel<<<dim3(C / 128, HW / 128, Bb), 256, SMEM_BYTES_NN>>>();
    proj_kernel<<<dim3(C / 128, NTOK / 128), 256, SMEM_BYTES_NN>>>(x, w_proj, b_proj, out);
}